// round 13
// baseline (speedup 1.0000x reference)
#include <cuda_runtime.h>
#include <cuda_bf16.h>

// Problem constants
#define Bn   4
#define Sn   512
#define Jn   24
#define Hn   128
#define NHn  8
#define HSn  16
#define HSP  18          // Q/K/V smem row stride (8B aligned)
#define WP   130         // transposed-weight row stride (conflict-free per pd)
#define OTP  66          // transposed-O row stride in kernel 2 (64 rows + pad)
#define LN_EPS 1e-5f

typedef unsigned long long u64;

// Scratch: attention head outputs in (B, S, J, NH*HS) layout
__device__ float g_heads[Bn * Sn * Jn * Hn];

// ---- packed f32x2 helpers ----
__device__ __forceinline__ u64 f2pack(float lo, float hi) {
    u64 r; asm("mov.b64 %0,{%1,%2};" : "=l"(r) : "f"(lo), "f"(hi)); return r;
}
__device__ __forceinline__ void f2unpack(u64 v, float& lo, float& hi) {
    asm("mov.b64 {%0,%1},%2;" : "=f"(lo), "=f"(hi) : "l"(v));
}
__device__ __forceinline__ u64 fma2(u64 a, u64 b, u64 c) {
    u64 d; asm("fma.rn.f32x2 %0,%1,%2,%3;" : "=l"(d) : "l"(a), "l"(b), "l"(c)); return d;
}
__device__ __forceinline__ u64 mul2(u64 a, u64 b) {
    u64 d; asm("mul.rn.f32x2 %0,%1,%2;" : "=l"(d) : "l"(a), "l"(b)); return d;
}
__device__ __forceinline__ float f2sum(u64 v) { float a, b; f2unpack(v, a, b); return a + b; }
__device__ __forceinline__ u64 lds2(const float* p) { return *reinterpret_cast<const u64*>(p); }

// ---------------------------------------------------------------------------
// Kernel 1: per (b, n, j) block — QKV projection + causal attention
//   grid = B*NH*J = 768 blocks, 256 threads
// ---------------------------------------------------------------------------
__global__ void __launch_bounds__(256, 1)
attn_kernel(const float* __restrict__ x,
            const float* __restrict__ qm,
            const float* __restrict__ km,
            const float* __restrict__ vm)
{
    extern __shared__ float sm[];
    float* Q   = sm;                    // Sn * HSP = 9216
    float* K   = Q + Sn * HSP;
    float* V   = K + Sn * HSP;
    float* Wqt = V + Sn * HSP;          // 16 * WP each
    float* Wkt = Wqt + HSn * WP;
    float* Wvt = Wkt + HSn * WP;
    float* Xt  = Wvt + HSn * WP;        // 64 * 128

    const int tid = threadIdx.x;
    const int blk = blockIdx.x;
    const int j = blk % Jn;
    const int n = (blk / Jn) % NHn;
    const int b = blk / (Jn * NHn);

    // --- Phase A: load weights transposed to [pd][h]; fold 0.25 into Wq ---
    const float* qmj = qm + ((n * Jn + j) * Hn) * HSn;
    const float* kmj = km + ((n * Jn + j) * Hn) * HSn;
    const float* vmj = vm + ((n * Jn + j) * Hn) * HSn;
    for (int i = tid; i < Hn * HSn; i += 256) {
        int h = i >> 4, pd_ = i & 15;
        Wqt[pd_ * WP + h] = qmj[i] * 0.25f;   // 1/sqrt(HS)
        Wkt[pd_ * WP + h] = kmj[i];
        Wvt[pd_ * WP + h] = vmj[i];
    }
    __syncthreads();

    // --- Phase B: QKV projection, 8 tiles of 64 rows, 4 rows per thread ---
    const int pr = tid >> 4;     // 0..15
    const int pd = tid & 15;     // 0..15
    const float* wq = Wqt + pd * WP;
    const float* wk = Wkt + pd * WP;
    const float* wv = Wvt + pd * WP;

    for (int t0 = 0; t0 < Sn; t0 += 64) {
        for (int i = tid; i < 64 * 32; i += 256) {
            int rr = i >> 5, c = i & 31;
            ((float4*)Xt)[i] = ((const float4*)(x + (((size_t)b * Sn + (t0 + rr)) * Jn + j) * Hn))[c];
        }
        __syncthreads();

        u64 aq[4] = {0,0,0,0}, ak[4] = {0,0,0,0}, av[4] = {0,0,0,0};
        #pragma unroll 8
        for (int h = 0; h < Hn; h += 2) {
            u64 wqv = lds2(wq + h);
            u64 wkv = lds2(wk + h);
            u64 wvv = lds2(wv + h);
            #pragma unroll
            for (int k = 0; k < 4; ++k) {
                u64 xv = lds2(Xt + (pr + 16 * k) * Hn + h);
                aq[k] = fma2(xv, wqv, aq[k]);
                ak[k] = fma2(xv, wkv, ak[k]);
                av[k] = fma2(xv, wvv, av[k]);
            }
        }
        #pragma unroll
        for (int k = 0; k < 4; ++k) {
            int s = t0 + pr + 16 * k;
            Q[s * HSP + pd] = f2sum(aq[k]);
            K[s * HSP + pd] = f2sum(ak[k]);
            V[s * HSP + pd] = f2sum(av[k]);
        }
        __syncthreads();
    }

    // --- Phase C: causal attention, lane = query, keys broadcast ---
    // warp -> group map balances fma cycles across SMSPs (pairs sum to 7+4? ->
    // SMSP s hosts warps s and s+4 -> groups s and 7-s, equal totals).
    const int warp = tid >> 5;
    const int lane = tid & 31;
    const int g = (warp < 4) ? warp : (11 - warp);   // 0..7
    const int qa = 64 * g + lane;
    const int qb = qa + 32;

    u64 qra[8], qrb[8];
    {
        const float* qpa = Q + qa * HSP;
        const float* qpb = Q + qb * HSP;
        #pragma unroll
        for (int i = 0; i < 8; ++i) {
            qra[i] = lds2(qpa + 2 * i);
            qrb[i] = lds2(qpb + 2 * i);
        }
    }

    u64 oa[8], ob[8];
    #pragma unroll
    for (int i = 0; i < 8; ++i) { oa[i] = 0ull; ob[i] = 0ull; }
    float suma = 0.f, sumb = 0.f;

    const int tend1 = 64 * g + 32;

    for (int t = 0; t < tend1; ++t) {
        const float* kp = K + t * HSP;
        u64 kk[8];
        #pragma unroll
        for (int i = 0; i < 8; ++i) kk[i] = lds2(kp + 2 * i);

        u64 da = mul2(qra[0], kk[0]);
        u64 db = mul2(qrb[0], kk[0]);
        #pragma unroll
        for (int i = 1; i < 8; ++i) {
            da = fma2(qra[i], kk[i], da);
            db = fma2(qrb[i], kk[i], db);
        }
        float ea = __expf(f2sum(da));
        float eb = __expf(f2sum(db));
        if (t > qa) ea = 0.f;            // qb >= tend1-? qb >= 64g+32 > t always
        suma += ea; sumb += eb;

        const float* vp = V + t * HSP;
        u64 ea2 = f2pack(ea, ea), eb2 = f2pack(eb, eb);
        #pragma unroll
        for (int i = 0; i < 8; ++i) {
            u64 vv = lds2(vp + 2 * i);
            oa[i] = fma2(ea2, vv, oa[i]);
            ob[i] = fma2(eb2, vv, ob[i]);
        }
    }
    // tail: only the upper 32 queries are active
    for (int t = tend1; t < tend1 + 32; ++t) {
        const float* kp = K + t * HSP;
        u64 kk[8];
        #pragma unroll
        for (int i = 0; i < 8; ++i) kk[i] = lds2(kp + 2 * i);
        u64 db = mul2(qrb[0], kk[0]);
        #pragma unroll
        for (int i = 1; i < 8; ++i) db = fma2(qrb[i], kk[i], db);
        float eb = __expf(f2sum(db));
        if (t > qb) eb = 0.f;
        sumb += eb;
        const float* vp = V + t * HSP;
        u64 eb2 = f2pack(eb, eb);
        #pragma unroll
        for (int i = 0; i < 8; ++i)
            ob[i] = fma2(eb2, lds2(vp + 2 * i), ob[i]);
    }

    // write: each lane owns rows qa, qb fully (no reductions)
    {
        float inva = 1.f / suma, invb = 1.f / sumb;
        float* pa = g_heads + (((size_t)b * Sn + qa) * Jn + j) * Hn + n * HSn;
        float* pb = g_heads + (((size_t)b * Sn + qb) * Jn + j) * Hn + n * HSn;
        #pragma unroll
        for (int c = 0; c < 4; ++c) {
            float a0, a1, a2, a3;
            f2unpack(oa[2 * c],     a0, a1);
            f2unpack(oa[2 * c + 1], a2, a3);
            ((float4*)pa)[c] = make_float4(a0 * inva, a1 * inva, a2 * inva, a3 * inva);
            float b0, b1, b2, b3;
            f2unpack(ob[2 * c],     b0, b1);
            f2unpack(ob[2 * c + 1], b2, b3);
            ((float4*)pb)[c] = make_float4(b0 * invb, b1 * invb, b2 * invb, b3 * invb);
        }
    }
}

// ---------------------------------------------------------------------------
// Kernel 2: per (j, 64-row tile) — output projection + residual + LayerNorm
//   grid = J * (B*S/64) = 768 blocks, 256 threads, 2 CTAs/SM
// ---------------------------------------------------------------------------
__global__ void __launch_bounds__(256, 2)
proj_ln_kernel(const float* __restrict__ x,
               const float* __restrict__ proj,
               const float* __restrict__ gamma,
               const float* __restrict__ beta,
               float* __restrict__ out)
{
    extern __shared__ float sm2[];
    float* P  = sm2;                 // Hn*Hn = 16384
    float* Ot = P + Hn * Hn;         // Hn * OTP (transposed O: [h][row]), 64 rows

    const int tid  = threadIdx.x;
    const int j    = blockIdx.x >> 5;
    const int tile = blockIdx.x & 31;
    const int m0   = tile * 64;

    const float* Pj = proj + j * Hn * Hn;
    for (int i = tid; i < Hn * Hn / 4; i += 256)
        ((float4*)P)[i] = ((const float4*)Pj)[i];
    for (int i = tid; i < 64 * Hn; i += 256) {
        int rr = i >> 7, h = i & 127;
        Ot[h * OTP + rr] = g_heads[((size_t)(m0 + rr) * Jn + j) * Hn + h];
    }
    __syncthreads();

    const int ty   = tid >> 5;          // warp: rows ty*8 .. ty*8+7
    const int lane = tid & 31;          // cols lane*4 .. lane*4+3
    const int rowbase = ty * 8;

    // acc[r][c] packs {row 2r, row 2r+1} for column lane*4+c
    u64 acc[4][4];
    #pragma unroll
    for (int r = 0; r < 4; ++r)
        #pragma unroll
        for (int c = 0; c < 4; ++c) acc[r][c] = 0ull;

    const float* obase = Ot + rowbase;
    #pragma unroll 4
    for (int h = 0; h < Hn; ++h) {
        float4 p = *(const float4*)(P + h * Hn + lane * 4);
        u64 d0 = f2pack(p.x, p.x);
        u64 d1 = f2pack(p.y, p.y);
        u64 d2 = f2pack(p.z, p.z);
        u64 d3 = f2pack(p.w, p.w);
        const float* oc = obase + h * OTP;
        #pragma unroll
        for (int r = 0; r < 4; ++r) {
            u64 ov = lds2(oc + 2 * r);
            acc[r][0] = fma2(ov, d0, acc[r][0]);
            acc[r][1] = fma2(ov, d1, acc[r][1]);
            acc[r][2] = fma2(ov, d2, acc[r][2]);
            acc[r][3] = fma2(ov, d3, acc[r][3]);
        }
    }

    // residual + LayerNorm, two rows (pair) at a time
    const float4 g  = *(const float4*)(gamma + lane * 4);
    const float4 bt = *(const float4*)(beta  + lane * 4);
    #pragma unroll
    for (int r = 0; r < 4; ++r) {
        const int row0 = rowbase + 2 * r;
        const float* xr = x + ((size_t)(m0 + row0) * Jn + j) * Hn + lane * 4;
        float4 xa = *(const float4*)xr;
        float4 xb = *(const float4*)(xr + Jn * Hn);

        float ve0, vo0, ve1, vo1, ve2, vo2, ve3, vo3;
        f2unpack(acc[r][0], ve0, vo0);
        f2unpack(acc[r][1], ve1, vo1);
        f2unpack(acc[r][2], ve2, vo2);
        f2unpack(acc[r][3], ve3, vo3);
        ve0 += xa.x; ve1 += xa.y; ve2 += xa.z; ve3 += xa.w;
        vo0 += xb.x; vo1 += xb.y; vo2 += xb.z; vo3 += xb.w;

        u64 ss = f2pack(ve0 + ve1 + ve2 + ve3, vo0 + vo1 + vo2 + vo3);
        u64 sq = f2pack(fmaf(ve0, ve0, fmaf(ve1, ve1, fmaf(ve2, ve2, ve3 * ve3))),
                        fmaf(vo0, vo0, fmaf(vo1, vo1, fmaf(vo2, vo2, vo3 * vo3))));
        #pragma unroll
        for (int o = 16; o; o >>= 1) {
            u64 s2 = __shfl_xor_sync(0xffffffffu, ss, o);
            u64 q2 = __shfl_xor_sync(0xffffffffu, sq, o);
            float sa, sb2, qa2, qb2, ca, cb, da, db;
            f2unpack(ss, sa, sb2); f2unpack(s2, ca, cb);
            f2unpack(sq, qa2, qb2); f2unpack(q2, da, db);
            ss = f2pack(sa + ca, sb2 + cb);
            sq = f2pack(qa2 + da, qb2 + db);
        }
        float se, so, qe, qo;
        f2unpack(ss, se, so);
        f2unpack(sq, qe, qo);
        float me = se * (1.f / 128.f), mo = so * (1.f / 128.f);
        float re = rsqrtf(qe * (1.f / 128.f) - me * me + LN_EPS);
        float ro = rsqrtf(qo * (1.f / 128.f) - mo * mo + LN_EPS);

        float* orow = out + ((size_t)(m0 + row0) * Jn + j) * Hn + lane * 4;
        float4 oa, ob;
        oa.x = (ve0 - me) * re * g.x + bt.x;
        oa.y = (ve1 - me) * re * g.y + bt.y;
        oa.z = (ve2 - me) * re * g.z + bt.z;
        oa.w = (ve3 - me) * re * g.w + bt.w;
        ob.x = (vo0 - mo) * ro * g.x + bt.x;
        ob.y = (vo1 - mo) * ro * g.y + bt.y;
        ob.z = (vo2 - mo) * ro * g.z + bt.z;
        ob.w = (vo3 - mo) * ro * g.w + bt.w;
        *(float4*)orow = oa;
        *(float4*)(orow + Jn * Hn) = ob;
    }
}

// ---------------------------------------------------------------------------
// Launch
// ---------------------------------------------------------------------------
extern "C" void kernel_launch(void* const* d_in, const int* in_sizes, int n_in,
                              void* d_out, int out_size)
{
    const float* x     = (const float*)d_in[0];
    // d_in[1] = mask (pure causal, handled analytically)
    const float* qm    = (const float*)d_in[2];
    const float* km    = (const float*)d_in[3];
    const float* vm    = (const float*)d_in[4];
    const float* proj  = (const float*)d_in[5];
    const float* gamma = (const float*)d_in[6];
    const float* beta  = (const float*)d_in[7];
    float* out = (float*)d_out;

    const int smem1 = (3 * Sn * HSP + 3 * HSn * WP + 64 * Hn) * (int)sizeof(float); // 168320
    const int smem2 = (Hn * Hn + Hn * OTP) * (int)sizeof(float);                    // 99328

    cudaFuncSetAttribute(attn_kernel, cudaFuncAttributeMaxDynamicSharedMemorySize, smem1);
    cudaFuncSetAttribute(proj_ln_kernel, cudaFuncAttributeMaxDynamicSharedMemorySize, smem2);

    attn_kernel<<<Bn * NHn * Jn, 256, smem1>>>(x, qm, km, vm);
    proj_ln_kernel<<<Jn * (Bn * Sn / 64), 256, smem2>>>(x, proj, gamma, beta, out);
}

// round 14
// speedup vs baseline: 1.0429x; 1.0429x over previous
#include <cuda_runtime.h>
#include <cuda_bf16.h>

// Problem constants
#define Bn   4
#define Sn   512
#define Jn   24
#define Hn   128
#define NHn  8
#define HSn  16
#define HSP  20          // Q/K/V smem row stride (16B-aligned rows for LDS.128)
#define WP   132         // transposed-weight row stride (16B-aligned)
#define OTP  66          // transposed-O row stride in kernel 2
#define LN_EPS 1e-5f

typedef unsigned long long u64;

// Scratch: attention head outputs in (B, S, J, NH*HS) layout
__device__ float g_heads[Bn * Sn * Jn * Hn];

// ---- packed f32x2 helpers ----
__device__ __forceinline__ u64 f2pack(float lo, float hi) {
    u64 r; asm("mov.b64 %0,{%1,%2};" : "=l"(r) : "f"(lo), "f"(hi)); return r;
}
__device__ __forceinline__ void f2unpack(u64 v, float& lo, float& hi) {
    asm("mov.b64 {%0,%1},%2;" : "=f"(lo), "=f"(hi) : "l"(v));
}
__device__ __forceinline__ u64 fma2(u64 a, u64 b, u64 c) {
    u64 d; asm("fma.rn.f32x2 %0,%1,%2,%3;" : "=l"(d) : "l"(a), "l"(b), "l"(c)); return d;
}
__device__ __forceinline__ u64 mul2(u64 a, u64 b) {
    u64 d; asm("mul.rn.f32x2 %0,%1,%2;" : "=l"(d) : "l"(a), "l"(b)); return d;
}
__device__ __forceinline__ float f2sum(u64 v) { float a, b; f2unpack(v, a, b); return a + b; }
__device__ __forceinline__ u64 lds2(const float* p) { return *reinterpret_cast<const u64*>(p); }

// load a 16-float row (16B aligned) as 8 packed f32x2 via 4x LDS.128
__device__ __forceinline__ void ldrow(const float* p, u64* r) {
    ulonglong2 a = *(const ulonglong2*)(p);
    ulonglong2 b = *(const ulonglong2*)(p + 4);
    ulonglong2 c = *(const ulonglong2*)(p + 8);
    ulonglong2 d = *(const ulonglong2*)(p + 12);
    r[0] = a.x; r[1] = a.y; r[2] = b.x; r[3] = b.y;
    r[4] = c.x; r[5] = c.y; r[6] = d.x; r[7] = d.y;
}

__device__ __forceinline__ float dot16(const u64* q, const u64* k) {
    u64 d = mul2(q[0], k[0]);
    #pragma unroll
    for (int i = 1; i < 8; ++i) d = fma2(q[i], k[i], d);
    return f2sum(d);
}

// ---------------------------------------------------------------------------
// Kernel 1: per (b, n, j) block — QKV projection + causal attention
//   grid = B*NH*J = 768 blocks, 256 threads
// ---------------------------------------------------------------------------
__global__ void __launch_bounds__(256, 1)
attn_kernel(const float* __restrict__ x,
            const float* __restrict__ qm,
            const float* __restrict__ km,
            const float* __restrict__ vm)
{
    extern __shared__ float sm[];
    float* Q   = sm;                    // Sn * HSP = 10240
    float* K   = Q + Sn * HSP;
    float* V   = K + Sn * HSP;
    float* Wqt = V + Sn * HSP;          // 16 * WP each
    float* Wkt = Wqt + HSn * WP;
    float* Wvt = Wkt + HSn * WP;
    float* Xt  = Wvt + HSn * WP;        // 64 * 128

    const int tid = threadIdx.x;
    const int blk = blockIdx.x;
    const int j = blk % Jn;
    const int n = (blk / Jn) % NHn;
    const int b = blk / (Jn * NHn);

    // --- Phase A: load weights transposed to [pd][h]; fold 0.25 into Wq ---
    const float* qmj = qm + ((n * Jn + j) * Hn) * HSn;
    const float* kmj = km + ((n * Jn + j) * Hn) * HSn;
    const float* vmj = vm + ((n * Jn + j) * Hn) * HSn;
    for (int i = tid; i < Hn * HSn; i += 256) {
        int h = i >> 4, pd_ = i & 15;
        Wqt[pd_ * WP + h] = qmj[i] * 0.25f;   // 1/sqrt(HS)
        Wkt[pd_ * WP + h] = kmj[i];
        Wvt[pd_ * WP + h] = vmj[i];
    }
    __syncthreads();

    // --- Phase B: QKV projection, 8 tiles of 64 rows, 4 rows per thread ---
    const int pr = tid >> 4;     // 0..15
    const int pd = tid & 15;     // 0..15
    const float* wq = Wqt + pd * WP;
    const float* wk = Wkt + pd * WP;
    const float* wv = Wvt + pd * WP;

    for (int t0 = 0; t0 < Sn; t0 += 64) {
        for (int i = tid; i < 64 * 32; i += 256) {
            int rr = i >> 5, c = i & 31;
            ((float4*)Xt)[i] = ((const float4*)(x + (((size_t)b * Sn + (t0 + rr)) * Jn + j) * Hn))[c];
        }
        __syncthreads();

        u64 aq[4] = {0,0,0,0}, ak[4] = {0,0,0,0}, av[4] = {0,0,0,0};
        #pragma unroll 4
        for (int h = 0; h < Hn; h += 4) {
            ulonglong2 wq2 = *(const ulonglong2*)(wq + h);
            ulonglong2 wk2 = *(const ulonglong2*)(wk + h);
            ulonglong2 wv2 = *(const ulonglong2*)(wv + h);
            #pragma unroll
            for (int k = 0; k < 4; ++k) {
                ulonglong2 xv = *(const ulonglong2*)(Xt + (pr + 16 * k) * Hn + h);
                aq[k] = fma2(xv.x, wq2.x, aq[k]);
                ak[k] = fma2(xv.x, wk2.x, ak[k]);
                av[k] = fma2(xv.x, wv2.x, av[k]);
                aq[k] = fma2(xv.y, wq2.y, aq[k]);
                ak[k] = fma2(xv.y, wk2.y, ak[k]);
                av[k] = fma2(xv.y, wv2.y, av[k]);
            }
        }
        #pragma unroll
        for (int k = 0; k < 4; ++k) {
            int s = t0 + pr + 16 * k;
            Q[s * HSP + pd] = f2sum(aq[k]);
            K[s * HSP + pd] = f2sum(ak[k]);
            V[s * HSP + pd] = f2sum(av[k]);
        }
        __syncthreads();
    }

    // --- Phase C: causal attention, lane = query, keys broadcast ---
    // SMSP s hosts warps s and s+4 -> groups s and 7-s (balanced work).
    const int warp = tid >> 5;
    const int lane = tid & 31;
    const int g = (warp < 4) ? warp : (11 - warp);   // 0..7
    const int qa = 64 * g + lane;
    const int qb = qa + 32;

    u64 qra[8], qrb[8];
    ldrow(Q + qa * HSP, qra);
    ldrow(Q + qb * HSP, qrb);

    u64 oa[8], ob[8];
    #pragma unroll
    for (int i = 0; i < 8; ++i) { oa[i] = 0ull; ob[i] = 0ull; }
    float suma = 0.f, sumb = 0.f;

    const int tmid = 64 * g;          // [0,tmid): both queries fully active

    // region 1: no masking
    for (int t = 0; t < tmid; t += 2) {
        u64 k0[8], k1[8];
        ldrow(K + t * HSP, k0);
        ldrow(K + (t + 1) * HSP, k1);
        float e00 = __expf(dot16(qra, k0));
        float e01 = __expf(dot16(qra, k1));
        float e10 = __expf(dot16(qrb, k0));
        float e11 = __expf(dot16(qrb, k1));
        suma += e00 + e01;
        sumb += e10 + e11;
        u64 v0[8], v1[8];
        ldrow(V + t * HSP, v0);
        ldrow(V + (t + 1) * HSP, v1);
        u64 p00 = f2pack(e00, e00), p01 = f2pack(e01, e01);
        u64 p10 = f2pack(e10, e10), p11 = f2pack(e11, e11);
        #pragma unroll
        for (int i = 0; i < 8; ++i) {
            oa[i] = fma2(p00, v0[i], oa[i]);
            oa[i] = fma2(p01, v1[i], oa[i]);
            ob[i] = fma2(p10, v0[i], ob[i]);
            ob[i] = fma2(p11, v1[i], ob[i]);
        }
    }
    // region 2: 32 steps, mask query-a only (qb always active)
    #pragma unroll 2
    for (int t = tmid; t < tmid + 32; t += 2) {
        u64 k0[8], k1[8];
        ldrow(K + t * HSP, k0);
        ldrow(K + (t + 1) * HSP, k1);
        float e00 = __expf(dot16(qra, k0));
        float e01 = __expf(dot16(qra, k1));
        float e10 = __expf(dot16(qrb, k0));
        float e11 = __expf(dot16(qrb, k1));
        if (t     > qa) e00 = 0.f;
        if (t + 1 > qa) e01 = 0.f;
        suma += e00 + e01;
        sumb += e10 + e11;
        u64 v0[8], v1[8];
        ldrow(V + t * HSP, v0);
        ldrow(V + (t + 1) * HSP, v1);
        u64 p00 = f2pack(e00, e00), p01 = f2pack(e01, e01);
        u64 p10 = f2pack(e10, e10), p11 = f2pack(e11, e11);
        #pragma unroll
        for (int i = 0; i < 8; ++i) {
            oa[i] = fma2(p00, v0[i], oa[i]);
            oa[i] = fma2(p01, v1[i], oa[i]);
            ob[i] = fma2(p10, v0[i], ob[i]);
            ob[i] = fma2(p11, v1[i], ob[i]);
        }
    }
    // region 3: 32 steps, query-b only, masked
    #pragma unroll 2
    for (int t = tmid + 32; t < tmid + 64; t += 2) {
        u64 k0[8], k1[8];
        ldrow(K + t * HSP, k0);
        ldrow(K + (t + 1) * HSP, k1);
        float e10 = __expf(dot16(qrb, k0));
        float e11 = __expf(dot16(qrb, k1));
        if (t     > qb) e10 = 0.f;
        if (t + 1 > qb) e11 = 0.f;
        sumb += e10 + e11;
        u64 v0[8], v1[8];
        ldrow(V + t * HSP, v0);
        ldrow(V + (t + 1) * HSP, v1);
        u64 p10 = f2pack(e10, e10), p11 = f2pack(e11, e11);
        #pragma unroll
        for (int i = 0; i < 8; ++i) {
            ob[i] = fma2(p10, v0[i], ob[i]);
            ob[i] = fma2(p11, v1[i], ob[i]);
        }
    }

    // write: each lane owns rows qa, qb fully (no reductions)
    {
        float inva = 1.f / suma, invb = 1.f / sumb;
        float* pa = g_heads + (((size_t)b * Sn + qa) * Jn + j) * Hn + n * HSn;
        float* pb = g_heads + (((size_t)b * Sn + qb) * Jn + j) * Hn + n * HSn;
        #pragma unroll
        for (int c = 0; c < 4; ++c) {
            float a0, a1, a2, a3;
            f2unpack(oa[2 * c],     a0, a1);
            f2unpack(oa[2 * c + 1], a2, a3);
            ((float4*)pa)[c] = make_float4(a0 * inva, a1 * inva, a2 * inva, a3 * inva);
            float b0, b1, b2, b3;
            f2unpack(ob[2 * c],     b0, b1);
            f2unpack(ob[2 * c + 1], b2, b3);
            ((float4*)pb)[c] = make_float4(b0 * invb, b1 * invb, b2 * invb, b3 * invb);
        }
    }
}

// ---------------------------------------------------------------------------
// Kernel 2: per (j, 64-row tile) — output projection + residual + LayerNorm
//   grid = J * (B*S/64) = 768 blocks, 256 threads, 2 CTAs/SM
// ---------------------------------------------------------------------------
__global__ void __launch_bounds__(256, 2)
proj_ln_kernel(const float* __restrict__ x,
               const float* __restrict__ proj,
               const float* __restrict__ gamma,
               const float* __restrict__ beta,
               float* __restrict__ out)
{
    extern __shared__ float sm2[];
    float* P  = sm2;                 // Hn*Hn = 16384
    float* Ot = P + Hn * Hn;         // Hn * OTP (transposed O: [h][row])

    const int tid  = threadIdx.x;
    const int j    = blockIdx.x >> 5;
    const int tile = blockIdx.x & 31;
    const int m0   = tile * 64;

    const float* Pj = proj + j * Hn * Hn;
    for (int i = tid; i < Hn * Hn / 4; i += 256)
        ((float4*)P)[i] = ((const float4*)Pj)[i];
    for (int i = tid; i < 64 * Hn; i += 256) {
        int rr = i >> 7, h = i & 127;
        Ot[h * OTP + rr] = g_heads[((size_t)(m0 + rr) * Jn + j) * Hn + h];
    }
    __syncthreads();

    const int ty   = tid >> 5;          // warp: rows ty*8 .. ty*8+7
    const int lane = tid & 31;          // cols lane*4 .. lane*4+3
    const int rowbase = ty * 8;

    u64 acc[4][4];
    #pragma unroll
    for (int r = 0; r < 4; ++r)
        #pragma unroll
        for (int c = 0; c < 4; ++c) acc[r][c] = 0ull;

    const float* obase = Ot + rowbase;
    #pragma unroll 4
    for (int h = 0; h < Hn; ++h) {
        float4 p = *(const float4*)(P + h * Hn + lane * 4);
        u64 d0 = f2pack(p.x, p.x);
        u64 d1 = f2pack(p.y, p.y);
        u64 d2 = f2pack(p.z, p.z);
        u64 d3 = f2pack(p.w, p.w);
        const float* oc = obase + h * OTP;
        #pragma unroll
        for (int r = 0; r < 4; ++r) {
            u64 ov = lds2(oc + 2 * r);
            acc[r][0] = fma2(ov, d0, acc[r][0]);
            acc[r][1] = fma2(ov, d1, acc[r][1]);
            acc[r][2] = fma2(ov, d2, acc[r][2]);
            acc[r][3] = fma2(ov, d3, acc[r][3]);
        }
    }

    // residual + LayerNorm, two rows (pair) at a time
    const float4 g  = *(const float4*)(gamma + lane * 4);
    const float4 bt = *(const float4*)(beta  + lane * 4);
    #pragma unroll
    for (int r = 0; r < 4; ++r) {
        const int row0 = rowbase + 2 * r;
        const float* xr = x + ((size_t)(m0 + row0) * Jn + j) * Hn + lane * 4;
        float4 xa = *(const float4*)xr;
        float4 xb = *(const float4*)(xr + Jn * Hn);

        float ve0, vo0, ve1, vo1, ve2, vo2, ve3, vo3;
        f2unpack(acc[r][0], ve0, vo0);
        f2unpack(acc[r][1], ve1, vo1);
        f2unpack(acc[r][2], ve2, vo2);
        f2unpack(acc[r][3], ve3, vo3);
        ve0 += xa.x; ve1 += xa.y; ve2 += xa.z; ve3 += xa.w;
        vo0 += xb.x; vo1 += xb.y; vo2 += xb.z; vo3 += xb.w;

        u64 ss = f2pack(ve0 + ve1 + ve2 + ve3, vo0 + vo1 + vo2 + vo3);
        u64 sq = f2pack(fmaf(ve0, ve0, fmaf(ve1, ve1, fmaf(ve2, ve2, ve3 * ve3))),
                        fmaf(vo0, vo0, fmaf(vo1, vo1, fmaf(vo2, vo2, vo3 * vo3))));
        #pragma unroll
        for (int o = 16; o; o >>= 1) {
            u64 s2 = __shfl_xor_sync(0xffffffffu, ss, o);
            u64 q2 = __shfl_xor_sync(0xffffffffu, sq, o);
            float sa, sb2, qa2, qb2, ca, cb, da, db;
            f2unpack(ss, sa, sb2); f2unpack(s2, ca, cb);
            f2unpack(sq, qa2, qb2); f2unpack(q2, da, db);
            ss = f2pack(sa + ca, sb2 + cb);
            sq = f2pack(qa2 + da, qb2 + db);
        }
        float se, so, qe, qo;
        f2unpack(ss, se, so);
        f2unpack(sq, qe, qo);
        float me = se * (1.f / 128.f), mo = so * (1.f / 128.f);
        float re = rsqrtf(qe * (1.f / 128.f) - me * me + LN_EPS);
        float ro = rsqrtf(qo * (1.f / 128.f) - mo * mo + LN_EPS);

        float* orow = out + ((size_t)(m0 + row0) * Jn + j) * Hn + lane * 4;
        float4 oa, ob;
        oa.x = (ve0 - me) * re * g.x + bt.x;
        oa.y = (ve1 - me) * re * g.y + bt.y;
        oa.z = (ve2 - me) * re * g.z + bt.z;
        oa.w = (ve3 - me) * re * g.w + bt.w;
        ob.x = (vo0 - mo) * ro * g.x + bt.x;
        ob.y = (vo1 - mo) * ro * g.y + bt.y;
        ob.z = (vo2 - mo) * ro * g.z + bt.z;
        ob.w = (vo3 - mo) * ro * g.w + bt.w;
        *(float4*)orow = oa;
        *(float4*)(orow + Jn * Hn) = ob;
    }
}

// ---------------------------------------------------------------------------
// Launch
// ---------------------------------------------------------------------------
extern "C" void kernel_launch(void* const* d_in, const int* in_sizes, int n_in,
                              void* d_out, int out_size)
{
    const float* x     = (const float*)d_in[0];
    // d_in[1] = mask (pure causal, handled analytically)
    const float* qm    = (const float*)d_in[2];
    const float* km    = (const float*)d_in[3];
    const float* vm    = (const float*)d_in[4];
    const float* proj  = (const float*)d_in[5];
    const float* gamma = (const float*)d_in[6];
    const float* beta  = (const float*)d_in[7];
    float* out = (float*)d_out;

    const int smem1 = (3 * Sn * HSP + 3 * HSn * WP + 64 * Hn) * (int)sizeof(float); // 180992
    const int smem2 = (Hn * Hn + Hn * OTP) * (int)sizeof(float);                    // 99328

    cudaFuncSetAttribute(attn_kernel, cudaFuncAttributeMaxDynamicSharedMemorySize, smem1);
    cudaFuncSetAttribute(proj_ln_kernel, cudaFuncAttributeMaxDynamicSharedMemorySize, smem2);

    attn_kernel<<<Bn * NHn * Jn, 256, smem1>>>(x, qm, km, vm);
    proj_ln_kernel<<<Jn * (Bn * Sn / 64), 256, smem2>>>(x, proj, gamma, beta, out);
}